// round 2
// baseline (speedup 1.0000x reference)
#include <cuda_runtime.h>
#include <cuda_bf16.h>

// 3x3 median blur, zero padding, 48 planes of 512x512 fp32.
// Each thread computes a 4-wide x 2-tall output tile:
//   - loads 4 rows as float4, halo columns via warp shuffle (boundary lanes
//     use predicated single-lane loads -> 1 L1 wavefront instead of 4)
//   - shared sorted-pair (r1,r2) serves both vertical windows; r0/r3 are
//     inserted into the sorted pair (4 ops) instead of a full sort3 (6 ops)
//   - median9 = med3( max3(column los), med3(column mids), min3(column his) )

constexpr int W = 512;
constexpr int H = 512;

__device__ __forceinline__ float med3f(float a, float b, float c) {
    return fmaxf(fminf(a, b), fminf(fmaxf(a, b), c));
}

// Load 6 contiguous columns [x0-1 .. x0+4] of row yy (zeros if out of range).
__device__ __forceinline__ void load6(const float* __restrict__ pb, int yy,
                                      int x0, int lane, float c[6]) {
    if (yy < 0 || yy >= H) {
        #pragma unroll
        for (int i = 0; i < 6; i++) c[i] = 0.0f;
        return;
    }
    const float* row = pb + yy * W;
    const float4 v = *reinterpret_cast<const float4*>(row + x0);
    // Halos come from neighbor lanes' registers (warp covers 128 contiguous cols).
    float left  = __shfl_up_sync(0xFFFFFFFFu, v.w, 1);
    float right = __shfl_down_sync(0xFFFFFFFFu, v.x, 1);
    if (lane == 0)  left  = (x0 > 0)     ? __ldg(row + x0 - 1) : 0.0f;
    if (lane == 31) right = (x0 + 4 < W) ? __ldg(row + x0 + 4) : 0.0f;
    c[0] = left; c[1] = v.x; c[2] = v.y; c[3] = v.z; c[4] = v.w; c[5] = right;
}

__device__ __forceinline__ void merge_store(const float lo[6], const float mi[6],
                                            const float hi[6], float* __restrict__ q) {
    float res[4];
    #pragma unroll
    for (int j = 0; j < 4; j++) {
        const float mx = fmaxf(fmaxf(lo[j], lo[j + 1]), lo[j + 2]);
        const float mn = fminf(fminf(hi[j], hi[j + 1]), hi[j + 2]);
        const float md = med3f(mi[j], mi[j + 1], mi[j + 2]);
        res[j] = med3f(mx, md, mn);
    }
    float4 o;
    o.x = res[0]; o.y = res[1]; o.z = res[2]; o.w = res[3];
    *reinterpret_cast<float4*>(q) = o;
}

__global__ void __launch_bounds__(512) median3x3_kernel(
    const float* __restrict__ in, float* __restrict__ out)
{
    const int plane = blockIdx.y;
    const int tx = threadIdx.x;           // 0..127, warp = 32 consecutive
    const int ty = threadIdx.y;           // 0..3
    const int y0 = (blockIdx.x * 4 + ty) * 2;  // output rows y0, y0+1
    const int x0 = tx * 4;
    const int lane = tx & 31;

    const float* pb = in  + (size_t)plane * (H * W);
    float*       qb = out + (size_t)plane * (H * W);

    // Four input rows, batched for MLP.
    float r0[6], r1[6], r2[6], r3[6];
    load6(pb, y0 - 1, x0, lane, r0);
    load6(pb, y0,     x0, lane, r1);
    load6(pb, y0 + 1, x0, lane, r2);
    load6(pb, y0 + 2, x0, lane, r3);

    // Shared sorted pair of the middle rows: a <= b.
    float a[6], b[6];
    #pragma unroll
    for (int i = 0; i < 6; i++) {
        a[i] = fminf(r1[i], r2[i]);
        b[i] = fmaxf(r1[i], r2[i]);
    }

    float lo[6], mi[6], hi[6];

    // Window A (rows y0-1, y0, y0+1): insert r0 into (a,b).
    #pragma unroll
    for (int i = 0; i < 6; i++) {
        lo[i] = fminf(a[i], r0[i]);
        hi[i] = fmaxf(b[i], r0[i]);
        mi[i] = fmaxf(a[i], fminf(b[i], r0[i]));
    }
    merge_store(lo, mi, hi, qb + (size_t)y0 * W + x0);

    // Window B (rows y0, y0+1, y0+2): insert r3 into (a,b).
    #pragma unroll
    for (int i = 0; i < 6; i++) {
        lo[i] = fminf(a[i], r3[i]);
        hi[i] = fmaxf(b[i], r3[i]);
        mi[i] = fmaxf(a[i], fminf(b[i], r3[i]));
    }
    merge_store(lo, mi, hi, qb + (size_t)(y0 + 1) * W + x0);
}

extern "C" void kernel_launch(void* const* d_in, const int* in_sizes, int n_in,
                              void* d_out, int out_size)
{
    const float* in  = (const float*)d_in[0];
    float*       out = (float*)d_out;

    // Block: 128 x-groups (4 px each) x 4 row-pairs -> 512x8 output tile.
    dim3 block(128, 4, 1);
    dim3 grid(512 / 8, 48, 1);
    median3x3_kernel<<<grid, block>>>(in, out);
}

// round 3
// speedup vs baseline: 1.1004x; 1.1004x over previous
#include <cuda_runtime.h>
#include <cuda_bf16.h>

// 3x3 median blur, zero padding, 48 planes of 512x512 fp32.
// R3: R1 structure (1 row x 4 cols per thread, proven fastest) with the
// strided halo LDG.32s replaced by aligned over-fetch: three coalesced
// LDG.128 per row (x0-4, x0, x0+4). The 3x line overlap hits in L1 within
// the warp, so DRAM traffic is unchanged while L1 wavefronts drop ~2.5x.

constexpr int W = 512;
constexpr int H = 512;

__device__ __forceinline__ float med3f(float a, float b, float c) {
    return fmaxf(fminf(a, b), fminf(fmaxf(a, b), c));
}

#define CE(a, b) do { float _t = fminf(a, b); (b) = fmaxf(a, b); (a) = _t; } while (0)

__global__ void __launch_bounds__(512) median3x3_kernel(
    const float* __restrict__ in, float* __restrict__ out)
{
    const int plane = blockIdx.y;                              // 0..47
    const int y     = blockIdx.x * blockDim.y + threadIdx.y;   // 0..511
    const int x0    = threadIdx.x * 4;                         // 0..508

    const float* p = in  + (size_t)plane * (H * W) + (size_t)y * W;
    float*       q = out + (size_t)plane * (H * W) + (size_t)y * W;

    const bool has_l = (x0 > 0);
    const bool has_r = (x0 < W - 4);
    const float4 z4 = make_float4(0.f, 0.f, 0.f, 0.f);

    // r[dy][i] : row y-1+dy, column x0-1+i  (i = 0..5)
    float r[3][6];
    #pragma unroll
    for (int dy = 0; dy < 3; dy++) {
        const int yy = y + dy - 1;
        if (yy < 0 || yy >= H) {
            #pragma unroll
            for (int i = 0; i < 6; i++) r[dy][i] = 0.0f;
        } else {
            const float* row = p + (dy - 1) * W;
            const float4 L = has_l ? *reinterpret_cast<const float4*>(row + x0 - 4) : z4;
            const float4 C =         *reinterpret_cast<const float4*>(row + x0);
            const float4 R = has_r ? *reinterpret_cast<const float4*>(row + x0 + 4) : z4;
            r[dy][0] = L.w;
            r[dy][1] = C.x; r[dy][2] = C.y; r[dy][3] = C.z; r[dy][4] = C.w;
            r[dy][5] = R.x;
        }
    }

    // Sort each column of 3: lo <= mi <= hi
    float lo[6], mi[6], hi[6];
    #pragma unroll
    for (int i = 0; i < 6; i++) {
        float a = r[0][i], b = r[1][i], c = r[2][i];
        CE(a, b); CE(b, c); CE(a, b);
        lo[i] = a; mi[i] = b; hi[i] = c;
    }

    // 4 outputs from overlapping column triples
    float res[4];
    #pragma unroll
    for (int j = 0; j < 4; j++) {
        const float mx = fmaxf(fmaxf(lo[j], lo[j + 1]), lo[j + 2]);
        const float mn = fminf(fminf(hi[j], hi[j + 1]), hi[j + 2]);
        const float md = med3f(mi[j], mi[j + 1], mi[j + 2]);
        res[j] = med3f(mx, md, mn);
    }

    float4 o;
    o.x = res[0]; o.y = res[1]; o.z = res[2]; o.w = res[3];
    *reinterpret_cast<float4*>(q + x0) = o;
}

extern "C" void kernel_launch(void* const* d_in, const int* in_sizes, int n_in,
                              void* d_out, int out_size)
{
    const float* in  = (const float*)d_in[0];
    float*       out = (float*)d_out;

    // Block: 128 x-groups (4 px each) x 4 rows -> 512x4 output tile.
    dim3 block(128, 4, 1);
    dim3 grid(512 / 4, 48, 1);
    median3x3_kernel<<<grid, block>>>(in, out);
}